// round 15
// baseline (speedup 1.0000x reference)
#include <cuda_runtime.h>
#include <cuda_bf16.h>

// CTC forward, two tasks (PyTorch semantics: blank=0, mean of loss/target_len,
// zero_infinity). One block per (task, batch) = 64 blocks x 32 threads (ONE warp).
//
// Single-warp wavefront: 14 extended-target slots per thread; alpha state is
// block-float-per-thread (14 fp32 mantissas + one int32 exponent; dead = 0).
// NO barriers, NO shared memory in the scan loop:
//  - cross-thread operand (left thread's slot 13) via __shfl_up
//  - softmax denominator computed inline (butterfly reduce + rcp), normalized
//    probs distributed via __shfl with precomputed source lanes
//  - all producer work (LDG, ex2, reduce, gather) pipelined >= 1 iteration ahead.

#define LOG2E 1.4426950408889634f
#define LN2   0.6931471805599453f
#define BATCH 32
#define TMAX  2000
#define NSLOT 14
#define NSYM  7
#define EMIN  (-(1 << 28))

static __device__ float        g_partial[64];
static __device__ unsigned int g_count = 0;

__device__ __forceinline__ float ex2(float x) {
    float y; asm("ex2.approx.f32 %0, %1;" : "=f"(y) : "f"(x)); return y;
}
__device__ __forceinline__ float lg2(float x) {
    float y; asm("lg2.approx.f32 %0, %1;" : "=f"(y) : "f"(x)); return y;
}
__device__ __forceinline__ float rcpf(float x) {
    float y; asm("rcp.approx.f32 %0, %1;" : "=f"(y) : "f"(x)); return y;
}
__device__ __forceinline__ float pow2c(int dp127) {   // 2^d, clamped both ends
    return __int_as_float(min(max(dp127, 0), 254) << 23);
}

__global__ void __launch_bounds__(32, 1)
ctc_forward_kernel(const float* __restrict__ elog, const float* __restrict__ plog,
                   const int* __restrict__ etgt, const int* __restrict__ ptgt,
                   const int* __restrict__ eil,  const int* __restrict__ pil,
                   const int* __restrict__ etl,  const int* __restrict__ ptl,
                   float* __restrict__ out)
{
    __shared__ float sFm[32 * NSLOT];
    __shared__ int   sFe[32];
    __shared__ int   sLast;

    const int task = blockIdx.x >> 5;   // 0 = error (C=4), 1 = phoneme (C=64)
    const int b    = blockIdx.x & 31;
    const int tidx = threadIdx.x;       // 0..31

    const float* logits;
    const int*   targets;
    int C, S, ilen, tlen;
    if (task == 0) {
        C = 4;  S = 50;
        logits  = elog + (size_t)b * TMAX * 4;
        targets = etgt + b * 50;
        ilen = eil[b]; tlen = etl[b];
    } else {
        C = 64; S = 200;
        logits  = plog + (size_t)b * TMAX * 64;
        targets = ptgt + b * 200;
        ilen = pil[b]; tlen = ptl[b];
    }
    const int Teff  = min(TMAX, max(ilen, 1));
    const int rlast = Teff - 1;

    // ---------- per-thread symbol metadata: l = 14*tidx + j ----------
    int   sl[NSYM];    // source lane of prob (column ext >> 1)
    int   par[NSYM];   // column parity (selects w0/w1)
    float skf[NSYM];   // skip multiplier (0.0 / 1.0)
    #pragma unroll
    for (int k = 0; k < NSYM; ++k) {
        int s  = NSYM * tidx + k;
        int sc = min(s, S - 1);
        int c1 = targets[sc];
        int c0 = targets[max(sc - 1, 0)];
        skf[k] = (s >= 1 && c1 != c0) ? 1.f : 0.f;
        sl[k]  = c1 >> 1;
        par[k] = c1 & 1;
    }

    const int  kk  = 2 * tidx;
    const bool kok = (kk < C);   // C even => kk,kk+1 both valid or neither

    // raw row load (one float2, coalesced)
    auto ldrow = [&](int r) -> float2 {
        float2 g = make_float2(0.f, 0.f);
        if (kok) g = *reinterpret_cast<const float2*>(logits + (size_t)r * C + kk);
        return g;
    };
    // normalized probs for a row, into (w0,w1) registers (warp-distributed)
    auto mkw = [&](float2 g, float& w0, float& w1) {
        float u0 = kok ? ex2(g.x * LOG2E) : 0.f;
        float u1 = kok ? ex2(g.y * LOG2E) : 0.f;
        float ss = u0 + u1;
        #pragma unroll
        for (int o = 16; o; o >>= 1) ss += __shfl_xor_sync(0xffffffffu, ss, o);
        float r_ = rcpf(ss);
        w0 = u0 * r_; w1 = u1 * r_;
    };

    // ---------- state ----------
    float m[NSLOT];
    #pragma unroll
    for (int j = 0; j < NSLOT; ++j) m[j] = 0.f;
    int  e = 0;
    bool live = false;

    float w0, w1, pb, p[NSYM];

    auto gather = [&](float a0, float a1) {
        pb = __shfl_sync(0xffffffffu, a0, 0);
        #pragma unroll
        for (int k = 0; k < NSYM; ++k) {
            float g0 = __shfl_sync(0xffffffffu, a0, sl[k]);
            float g1 = __shfl_sync(0xffffffffu, a1, sl[k]);
            p[k] = par[k] ? g1 : g0;
        }
    };

    // ---------- prologue ----------
    mkw(ldrow(0), w0, w1);
    gather(w0, w1);                       // row 0 probs
    if (tidx == 0) { m[0] = pb; m[1] = p[0]; live = true; }

    mkw(ldrow(min(1, rlast)), w0, w1);
    gather(w0, w1);                       // probs for step 1 -> (pb, p)
    mkw(ldrow(min(2, rlast)), w0, w1);    // w = row 2 (= t+1 for t=1)
    float2 y = ldrow(min(3, rlast));      // raw row t+2
    float2 z = ldrow(min(4, rlast));      // raw row t+3 in flight

    // ---------- forward scan (no sync of any kind) ----------
    for (int t = 1; t < Teff; ++t) {
        // (a) probs for row t+2 from raw y (1-iter slack before use)
        float u0 = kok ? ex2(y.x * LOG2E) : 0.f;
        float u1 = kok ? ex2(y.y * LOG2E) : 0.f;
        float ss = u0 + u1;
        #pragma unroll
        for (int o = 16; o; o >>= 1) ss += __shfl_xor_sync(0xffffffffu, ss, o);
        float rr = rcpf(ss);
        float nw0 = u0 * rr, nw1 = u1 * rr;

        // (b) advance raw pipeline (3-iter LDG lead)
        y = z;
        z = ldrow(min(t + 4, rlast));

        // (c) neighbor operand (left thread's OLD slot 13)
        float nm = __shfl_up_sync(0xffffffffu, m[NSLOT - 1], 1);
        int   ne = __shfl_up_sync(0xffffffffu, e, 1);
        if (tidx == 0) nm = 0.f;

        if (!live) e = ne;
        int d = ne - e;
        if (d > 100) {                    // neighbor dominates: rebase (rare)
            float rb = pow2c(e - ne + 127);
            #pragma unroll
            for (int j = 0; j < NSLOT; ++j) m[j] *= rb;
            e = ne; d = 0;
        }
        float an = nm * pow2c(d + 127);

        // (d) recurrence: all terms share exponent basis e
        float n[NSLOT];
        n[0] = pb   * (m[0] + an);
        n[1] = p[0] * fmaf(skf[0], an, m[1] + m[0]);
        #pragma unroll
        for (int k = 1; k < NSYM; ++k) {
            n[2 * k]     = pb   * (m[2 * k] + m[2 * k - 1]);
            n[2 * k + 1] = p[k] * fmaf(skf[k], m[2 * k - 1],
                                       m[2 * k + 1] + m[2 * k]);
        }

        // (e) block renorm: max mantissa -> [1,2)
        float mm = n[0];
        #pragma unroll
        for (int j = 1; j < NSLOT; ++j) mm = fmaxf(mm, n[j]);
        int bb = __float_as_int(mm);
        live = (bb != 0);
        int sh = live ? ((bb >> 23) - 127) : 0;
        float rs = __int_as_float((127 - sh) << 23);
        #pragma unroll
        for (int j = 0; j < NSLOT; ++j) m[j] = n[j] * rs;
        e += sh;

        // (f) gather probs for step t+1 from w (row t+1, made last iter)
        gather(w0, w1);
        w0 = nw0; w1 = nw1;
    }

    // ---------- publish finals ----------
    #pragma unroll
    for (int j = 0; j < NSLOT; ++j) sFm[tidx * NSLOT + j] = m[j];
    sFe[tidx] = e;
    __syncthreads();

    // ---------- loss + fused deterministic reduction ----------
    if (tidx == 0) {
        const int iL = 2 * tlen - 1, iB = 2 * tlen;
        float mL = sFm[iL], mB = sFm[iB];
        int   eL = (mL > 0.f) ? sFe[iL / NSLOT] : EMIN;
        int   eB = (mB > 0.f) ? sFe[iB / NSLOT] : EMIN;
        int   em = max(eL, eB);
        float s2 = mL * pow2c(eL + 127 - em) + mB * pow2c(eB + 127 - em);
        float loss = (s2 > 0.f && em > EMIN / 2)
                   ? -((float)em + lg2(s2)) * LN2 : 0.f;
        if (!(loss <= 1e29f)) loss = 0.f;           // zero_infinity / NaN
        g_partial[blockIdx.x] = loss / (float)tlen * (1.0f / BATCH);
        __threadfence();
        unsigned tk = atomicAdd(&g_count, 1u);
        sLast = (tk == 63u);
    }
    __syncthreads();
    if (sLast && tidx == 0) {
        __threadfence();
        float s = 0.f;
        #pragma unroll
        for (int i = 0; i < 64; ++i) {
            float v;
            asm volatile("ld.global.cg.f32 %0, [%1];" : "=f"(v) : "l"(g_partial + i));
            s += v;
        }
        out[0] = s;
        g_count = 0;   // reset for graph replay
    }
}

extern "C" void kernel_launch(void* const* d_in, const int* in_sizes, int n_in,
                              void* d_out, int out_size)
{
    const float* elog = (const float*)d_in[0];
    const float* plog = (const float*)d_in[1];
    const int*   etgt = (const int*)d_in[2];
    const int*   ptgt = (const int*)d_in[3];
    const int*   eil  = (const int*)d_in[4];
    const int*   pil  = (const int*)d_in[5];
    const int*   etl  = (const int*)d_in[6];
    const int*   ptl  = (const int*)d_in[7];
    float* out = (float*)d_out;

    ctc_forward_kernel<<<64, 32>>>(elog, plog, etgt, ptgt,
                                   eil, pil, etl, ptl, out);
}

// round 16
// speedup vs baseline: 1.1829x; 1.1829x over previous
#include <cuda_runtime.h>
#include <cuda_bf16.h>

// CTC forward, two tasks (PyTorch semantics: blank=0, mean of loss/target_len,
// zero_infinity). One block per (task, batch) = 64 blocks x 32 threads (ONE warp).
//
// Single-warp wavefront, 14 slots/thread, block-float-per-thread state
// (14 fp32 mantissas + one int32 exponent; dead = 0). No barriers.
// Softmax probs computed inline (ex2 + 5-shfl butterfly + rcp) and
// distributed through a 2x64-float smem double buffer: producers do 2 STS,
// consumers prefetch 8 LDS one iteration ahead (replaces 15 shuffles/step).
// One __syncwarp per step orders STS -> LDS within the warp.

#define LOG2E 1.4426950408889634f
#define LN2   0.6931471805599453f
#define BATCH 32
#define TMAX  2000
#define NSLOT 14
#define NSYM  7
#define EMIN  (-(1 << 28))

static __device__ float        g_partial[64];
static __device__ unsigned int g_count = 0;

__device__ __forceinline__ float ex2(float x) {
    float y; asm("ex2.approx.f32 %0, %1;" : "=f"(y) : "f"(x)); return y;
}
__device__ __forceinline__ float lg2(float x) {
    float y; asm("lg2.approx.f32 %0, %1;" : "=f"(y) : "f"(x)); return y;
}
__device__ __forceinline__ float rcpf(float x) {
    float y; asm("rcp.approx.f32 %0, %1;" : "=f"(y) : "f"(x)); return y;
}
__device__ __forceinline__ float pow2c(int dp127) {   // 2^d, clamped both ends
    return __int_as_float(min(max(dp127, 0), 254) << 23);
}

__global__ void __launch_bounds__(32, 1)
ctc_forward_kernel(const float* __restrict__ elog, const float* __restrict__ plog,
                   const int* __restrict__ etgt, const int* __restrict__ ptgt,
                   const int* __restrict__ eil,  const int* __restrict__ pil,
                   const int* __restrict__ etl,  const int* __restrict__ ptl,
                   float* __restrict__ out)
{
    __shared__ float sW[2][64];          // prob rows, double-buffered
    __shared__ float sFm[32 * NSLOT];
    __shared__ int   sFe[32];
    __shared__ int   sLast;

    const int task = blockIdx.x >> 5;    // 0 = error (C=4), 1 = phoneme (C=64)
    const int b    = blockIdx.x & 31;
    const int tidx = threadIdx.x;        // 0..31

    const float* logits;
    const int*   targets;
    int C, S, ilen, tlen;
    if (task == 0) {
        C = 4;  S = 50;
        logits  = elog + (size_t)b * TMAX * 4;
        targets = etgt + b * 50;
        ilen = eil[b]; tlen = etl[b];
    } else {
        C = 64; S = 200;
        logits  = plog + (size_t)b * TMAX * 64;
        targets = ptgt + b * 200;
        ilen = pil[b]; tlen = ptl[b];
    }
    const int Teff  = min(TMAX, max(ilen, 1));
    const int rlast = Teff - 1;

    // ---------- per-thread symbol metadata: l = 14*tidx + j ----------
    int   extc[NSYM];  // full class index of each odd slot's symbol
    float skf[NSYM];   // skip multiplier (0.0 / 1.0)
    #pragma unroll
    for (int k = 0; k < NSYM; ++k) {
        int s  = NSYM * tidx + k;
        int sc = min(s, S - 1);
        int c1 = targets[sc];
        int c0 = targets[max(sc - 1, 0)];
        skf[k]  = (s >= 1 && c1 != c0) ? 1.f : 0.f;
        extc[k] = c1;
    }

    const int  kk  = 2 * tidx;
    const bool kok = (kk < C);           // C even: kk,kk+1 both valid or neither

    auto ldrow = [&](int r) -> float2 {
        float2 g = make_float2(0.f, 0.f);
        if (kok) g = *reinterpret_cast<const float2*>(logits + (size_t)r * C + kk);
        return g;
    };

    // ---------- state ----------
    float m[NSLOT];
    #pragma unroll
    for (int j = 0; j < NSLOT; ++j) m[j] = 0.f;
    int  e = 0;
    bool live = false;

    // ---------- prologue ----------
    {   // row 0 probs, init m[0], m[1] on lane 0
        float2 g = ldrow(0);
        float u0 = kok ? ex2(g.x * LOG2E) : 0.f;
        float u1 = kok ? ex2(g.y * LOG2E) : 0.f;
        float ss = u0 + u1;
        #pragma unroll
        for (int o = 16; o; o >>= 1) ss += __shfl_xor_sync(0xffffffffu, ss, o);
        float r_ = rcpf(ss);
        int c1 = targets[0];
        float q0 = __shfl_sync(0xffffffffu, u0, c1 >> 1);
        float q1 = __shfl_sync(0xffffffffu, u1, c1 >> 1);
        if (tidx == 0) {
            m[0] = u0 * r_;                       // blank prob = w[0]
            m[1] = ((c1 & 1) ? q1 : q0) * r_;
            live = true;
        }
    }

    // stage rows 1 and 2 into sW[1], sW[0]
    #pragma unroll
    for (int r0 = 1; r0 <= 2; ++r0) {
        float2 g = ldrow(min(r0, rlast));
        float u0 = kok ? ex2(g.x * LOG2E) : 0.f;
        float u1 = kok ? ex2(g.y * LOG2E) : 0.f;
        float ss = u0 + u1;
        #pragma unroll
        for (int o = 16; o; o >>= 1) ss += __shfl_xor_sync(0xffffffffu, ss, o);
        float r_ = rcpf(ss);
        if (kok) { sW[r0 & 1][kk] = u0 * r_; sW[r0 & 1][kk + 1] = u1 * r_; }
    }
    __syncwarp();

    // gather probs for step 1 from sW[1]
    float pb = sW[1][0];
    float p[NSYM];
    #pragma unroll
    for (int k = 0; k < NSYM; ++k) p[k] = sW[1][extc[k]];

    float2 y = ldrow(min(3, rlast));   // raw row t+2 (t=1)
    float2 z = ldrow(min(4, rlast));   // raw row t+3 in flight

    // ---------- forward scan (single warp, no barriers) ----------
    for (int t = 1; t < Teff; ++t) {
        // (a) probs for row t+2 -> sW[t&1]
        float u0 = kok ? ex2(y.x * LOG2E) : 0.f;
        float u1 = kok ? ex2(y.y * LOG2E) : 0.f;
        float ss = u0 + u1;
        #pragma unroll
        for (int o = 16; o; o >>= 1) ss += __shfl_xor_sync(0xffffffffu, ss, o);
        float rr = rcpf(ss);
        if (kok) { sW[t & 1][kk] = u0 * rr; sW[t & 1][kk + 1] = u1 * rr; }

        // (b) advance raw LDG pipeline (3-iter lead)
        y = z;
        z = ldrow(min(t + 4, rlast));

        // (c) neighbor operand (left thread's OLD slot 13)
        float nm = __shfl_up_sync(0xffffffffu, m[NSLOT - 1], 1);
        int   ne = __shfl_up_sync(0xffffffffu, e, 1);
        if (tidx == 0) nm = 0.f;

        if (!live) e = ne;
        int d = ne - e;
        if (d > 100) {                  // neighbor dominates: rebase (rare)
            float rb = pow2c(e - ne + 127);
            #pragma unroll
            for (int j = 0; j < NSLOT; ++j) m[j] *= rb;
            e = ne; d = 0;
        }
        float an = nm * pow2c(d + 127);

        // (d) recurrence: all terms share exponent basis e
        float n[NSLOT];
        n[0] = pb   * (m[0] + an);
        n[1] = p[0] * fmaf(skf[0], an, m[1] + m[0]);
        #pragma unroll
        for (int k = 1; k < NSYM; ++k) {
            n[2 * k]     = pb   * (m[2 * k] + m[2 * k - 1]);
            n[2 * k + 1] = p[k] * fmaf(skf[k], m[2 * k - 1],
                                       m[2 * k + 1] + m[2 * k]);
        }

        // (e) block renorm: max mantissa -> [1,2)
        float mm = n[0];
        #pragma unroll
        for (int j = 1; j < NSLOT; ++j) mm = fmaxf(mm, n[j]);
        int bb = __float_as_int(mm);
        live = (bb != 0);
        int sh = live ? ((bb >> 23) - 127) : 0;
        float rs = __int_as_float((127 - sh) << 23);
        #pragma unroll
        for (int j = 0; j < NSLOT; ++j) m[j] = n[j] * rs;
        e += sh;

        // (f) prefetch probs for step t+1 from sW[(t+1)&1] (row t+1)
        __syncwarp();
        {
            const float* wrow = sW[(t + 1) & 1];
            pb = wrow[0];
            #pragma unroll
            for (int k = 0; k < NSYM; ++k) p[k] = wrow[extc[k]];
        }
    }

    // ---------- publish finals ----------
    #pragma unroll
    for (int j = 0; j < NSLOT; ++j) sFm[tidx * NSLOT + j] = m[j];
    sFe[tidx] = e;
    __syncwarp();

    // ---------- loss + fused deterministic reduction ----------
    if (tidx == 0) {
        const int iL = 2 * tlen - 1, iB = 2 * tlen;
        float mL = sFm[iL], mB = sFm[iB];
        int   eL = (mL > 0.f) ? sFe[iL / NSLOT] : EMIN;
        int   eB = (mB > 0.f) ? sFe[iB / NSLOT] : EMIN;
        int   em = max(eL, eB);
        float s2 = mL * pow2c(eL + 127 - em) + mB * pow2c(eB + 127 - em);
        float loss = (s2 > 0.f && em > EMIN / 2)
                   ? -((float)em + lg2(s2)) * LN2 : 0.f;
        if (!(loss <= 1e29f)) loss = 0.f;           // zero_infinity / NaN
        g_partial[blockIdx.x] = loss / (float)tlen * (1.0f / BATCH);
        __threadfence();
        unsigned tk = atomicAdd(&g_count, 1u);
        sLast = (tk == 63u);
    }
    __syncwarp();
    if (sLast && tidx == 0) {
        __threadfence();
        float s = 0.f;
        #pragma unroll
        for (int i = 0; i < 64; ++i) {
            float v;
            asm volatile("ld.global.cg.f32 %0, [%1];" : "=f"(v) : "l"(g_partial + i));
            s += v;
        }
        out[0] = s;
        g_count = 0;   // reset for graph replay
    }
}

extern "C" void kernel_launch(void* const* d_in, const int* in_sizes, int n_in,
                              void* d_out, int out_size)
{
    const float* elog = (const float*)d_in[0];
    const float* plog = (const float*)d_in[1];
    const int*   etgt = (const int*)d_in[2];
    const int*   ptgt = (const int*)d_in[3];
    const int*   eil  = (const int*)d_in[4];
    const int*   pil  = (const int*)d_in[5];
    const int*   etl  = (const int*)d_in[6];
    const int*   ptl  = (const int*)d_in[7];
    float* out = (float*)d_out;

    ctc_forward_kernel<<<64, 32>>>(elog, plog, etgt, ptgt,
                                   eil, pil, etl, ptl, out);
}